// round 6
// baseline (speedup 1.0000x reference)
#include <cuda_runtime.h>

typedef unsigned long long ull;

// Problem: X[8,256,128], W1[128,128], W2[128,128], v[128] -> out[8,256,256]
#define BB   8
#define DD   256
#define DIM  128
#define GRID 1024

// Scratch (__device__ globals)
__device__ float  g_W1T[DIM * DIM];              // [k][m]
__device__ float  g_W2T[DIM * DIM];              // [k][m]
__device__ float4 g_EaTq[BB * 64 * DIM];         // [(b*64+jq)*128+m] = (a_j0..a_j3)
__device__ float  g_Ec4 [BB * 32 * DD * 4 + 1024]; // [b][g=m/4][d][m%4]
__device__ unsigned g_cnt[2];                    // monotonic barrier counters

// ---- packed f32x2 helpers (Blackwell) --------------------------------------
__device__ __forceinline__ ull fma2(ull a, ull b, ull c) {
    ull d; asm("fma.rn.f32x2 %0,%1,%2,%3;" : "=l"(d) : "l"(a), "l"(b), "l"(c)); return d;
}
__device__ __forceinline__ ull mul2(ull a, ull b) {
    ull d; asm("mul.rn.f32x2 %0,%1,%2;" : "=l"(d) : "l"(a), "l"(b)); return d;
}
__device__ __forceinline__ ull dup2(float x) {
    ull d; asm("mov.b64 %0,{%1,%1};" : "=l"(d) : "f"(x)); return d;
}
__device__ __forceinline__ float2 unpk(ull a) {
    float2 r; asm("mov.b64 {%0,%1},%2;" : "=f"(r.x), "=f"(r.y) : "l"(a)); return r;
}
__device__ __forceinline__ ull pk(float x, float y) {
    ull d; asm("mov.b64 %0,{%1,%2};" : "=l"(d) : "f"(x), "f"(y)); return d;
}
__device__ __forceinline__ float frcp(float x) {
    float r; asm("rcp.approx.f32 %0,%1;" : "=f"(r) : "f"(x)); return r;
}
__device__ __forceinline__ void cp16(unsigned smem_dst, const void* gsrc) {
    asm volatile("cp.async.cg.shared.global [%0], [%1], 16;"
                 :: "r"(smem_dst), "l"(gsrc) : "memory");
}
__device__ __forceinline__ void cp_commit() {
    asm volatile("cp.async.commit_group;" ::: "memory");
}
template<int N> __device__ __forceinline__ void cp_wait() {
    asm volatile("cp.async.wait_group %0;" :: "n"(N) : "memory");
}

// Grid barrier: monotonic generation counter (no reset -> replay-safe;
// wrap-safe comparison). All GRID blocks are co-resident by construction.
__device__ __forceinline__ void gbar(int i) {
    __threadfence();
    __syncthreads();
    if (threadIdx.x == 0) {
        unsigned old = atomicAdd(&g_cnt[i], 1u);
        unsigned target = old - (old % GRID) + GRID;   // end of this round
        while ((int)(*(volatile unsigned*)&g_cnt[i] - target) < 0)
            __nanosleep(32);
    }
    __syncthreads();
}

// ---------------------------------------------------------------------------
// Fused kernel: grid = 1024 x 128 threads, occ 8 (single wave, 1184 slots).
//  Phase 0: W transpose (256 blocks) + vD staging.
//  Phase A: 512 blocks x 2 same-matrix row-quads: GEMM + exp(2*) -> scratch.
//  Phase B: pairwise: out = Vsum - 2*sum_m v_m/(Ea*Ec+1), 1 rcp per 4 m,
//           packed FFMA2, cp.async Ec ring, coalesced output via smem.
// ---------------------------------------------------------------------------
__global__ void __launch_bounds__(128, 8) fused_pairwise(
    const float* __restrict__ X,
    const float* __restrict__ W1,
    const float* __restrict__ W2,
    const float* __restrict__ v,
    float* __restrict__ out)
{
    __shared__ __align__(16) float4 ring[8 * 128];   // 16KB: Xq (A) / Ec ring & Os (B)
    __shared__ __align__(16) float4 EaTf4[DIM];      // [m] -> (a_j0..a_j3)
    __shared__ __align__(16) float2 vD[DIM];         // duplicated v

    const int t   = threadIdx.x;
    const int bid = blockIdx.x;

    // ---------------- Phase 0: W transpose + v staging ----------------------
    if (bid < 256) {
        const int mat  = bid >> 7;
        const int mrow = bid & 127;
        const float* W = mat ? W2 : W1;
        float w = W[mrow * DIM + t];                 // coalesced read
        (mat ? g_W2T : g_W1T)[t * DIM + mrow] = w;   // scattered write (tiny)
    }
    {
        float vv = v[t];
        vD[t] = make_float2(vv, vv);
    }
    gbar(0);

    // ---------------- Phase A: GEMM + exp -----------------------------------
    if (bid < 512) {
        const int isEa = (bid < 256);
        const int w0   = isEa ? bid : (bid - 256);
        const float* WT = isEa ? g_W1T : g_W2T;
        float* Xqf = (float*)ring;                    // 2 quads x [k] float4

        int bq[2], r0[2];
        #pragma unroll
        for (int h = 0; h < 2; h++) {
            int q = 2 * w0 + h;
            bq[h] = q >> 6;
            r0[h] = (q & 63) * 4;
            // stage 4 X rows of quad h, transposed into Xqf[h]
            int row = t >> 5, qd = t & 31;
            float4 xv = ((const float4*)X)[(size_t)(bq[h] * DD + r0[h] + row) * 32 + qd];
            float* dst = Xqf + h * 512;
            dst[(qd * 4 + 0) * 4 + row] = xv.x;
            dst[(qd * 4 + 1) * 4 + row] = xv.y;
            dst[(qd * 4 + 2) * 4 + row] = xv.z;
            dst[(qd * 4 + 3) * 4 + row] = xv.w;
        }
        __syncthreads();

        ull a0 = dup2(0.0f), a1 = dup2(0.0f), a2 = dup2(0.0f), a3 = dup2(0.0f);
        #pragma unroll 8
        for (int k = 0; k < DIM; k++) {
            float w = __ldg(&WT[k * DIM + t]);        // coalesced (lane = m)
            ull dw = dup2(w);
            ulonglong2 x0 = *(const ulonglong2*)(Xqf + k * 4);
            ulonglong2 x1 = *(const ulonglong2*)(Xqf + 512 + k * 4);
            a0 = fma2(x0.x, dw, a0);
            a1 = fma2(x0.y, dw, a1);
            a2 = fma2(x1.x, dw, a2);
            a3 = fma2(x1.y, dw, a3);
        }

        float2 p0 = unpk(a0), p1 = unpk(a1), p2 = unpk(a2), p3 = unpk(a3);
        float e[8] = { __expf(2.0f * p0.x), __expf(2.0f * p0.y),
                       __expf(2.0f * p1.x), __expf(2.0f * p1.y),
                       __expf(2.0f * p2.x), __expf(2.0f * p2.y),
                       __expf(2.0f * p3.x), __expf(2.0f * p3.y) };

        #pragma unroll
        for (int h = 0; h < 2; h++) {
            if (isEa) {
                g_EaTq[(size_t)(bq[h] * 64 + (2 * w0 + h & 63)) * DIM + t] =
                    make_float4(e[4*h+0], e[4*h+1], e[4*h+2], e[4*h+3]);
            } else {
                size_t base = ((size_t)(bq[h] * 32 + (t >> 2)) * DD) * 4 + (t & 3);
                #pragma unroll
                for (int r = 0; r < 4; r++)
                    g_Ec4[base + (size_t)(r0[h] + r) * 4] = e[4*h + r];
            }
        }
    }
    gbar(1);

    // ---------------- Phase B: pairwise --------------------------------------
    const int kt = bid & 1;
    const int jg = (bid >> 1) & 63;
    const int b  = bid >> 7;
    const int j0 = jg * 4;
    const int k  = kt * 128 + t;

    EaTf4[t] = g_EaTq[(size_t)(b * 64 + jg) * DIM + t];

    const float4* ecq = (const float4*)g_Ec4 + (size_t)(b * 32) * DD + k;
    unsigned rb = (unsigned)__cvta_generic_to_shared(ring) + t * 16;

    #pragma unroll
    for (int s = 0; s < 7; s++) {
        cp16(rb + (s & 7) * 2048, ecq + (size_t)s * DD);
        cp_commit();
    }

    float Vsum = 0.0f;
    #pragma unroll 16
    for (int m4 = 0; m4 < 64; m4++) {
        float4 q = ((const float4*)vD)[m4];
        Vsum += q.x + q.z;
    }
    __syncthreads();                       // EaTf4 visible

    const ull ONE2 = dup2(1.0f);
    ull acc0 = dup2(0.0f), acc1 = dup2(0.0f);

    #pragma unroll 8
    for (int g = 0; g < 32; g++) {
        cp_wait<6>();
        float4 E = ring[(g & 7) * 128 + t];
        if (g < 25)
            cp16(rb + ((g + 7) & 7) * 2048, ecq + (size_t)(g + 7) * DD);
        cp_commit();

        ull ec0 = dup2(E.x), ec1 = dup2(E.y), ec2 = dup2(E.z), ec3 = dup2(E.w);
        const ulonglong2* eap = (const ulonglong2*)(EaTf4 + 4 * g);
        ulonglong2 ea0 = eap[0], ea1 = eap[1], ea2 = eap[2], ea3 = eap[3];
        ulonglong2 vab = ((const ulonglong2*)vD)[2 * g];
        ulonglong2 vcd = ((const ulonglong2*)vD)[2 * g + 1];

        {   // j-pair (j0,j1)
            ull q0 = fma2(ea0.x, ec0, ONE2);
            ull q1 = fma2(ea1.x, ec1, ONE2);
            ull q2 = fma2(ea2.x, ec2, ONE2);
            ull q3 = fma2(ea3.x, ec3, ONE2);
            ull d01 = mul2(q0, q1), d23 = mul2(q2, q3);
            ull n01 = mul2(vab.x, q1); n01 = fma2(vab.y, q0, n01);
            ull n23 = mul2(vcd.x, q3); n23 = fma2(vcd.y, q2, n23);
            ull den = mul2(d01, d23);
            ull num = mul2(n01, d23); num = fma2(n23, d01, num);
            float2 dd = unpk(den);
            ull rr = pk(frcp(dd.x), frcp(dd.y));
            acc0 = fma2(num, rr, acc0);
        }
        {   // j-pair (j2,j3)
            ull q0 = fma2(ea0.y, ec0, ONE2);
            ull q1 = fma2(ea1.y, ec1, ONE2);
            ull q2 = fma2(ea2.y, ec2, ONE2);
            ull q3 = fma2(ea3.y, ec3, ONE2);
            ull d01 = mul2(q0, q1), d23 = mul2(q2, q3);
            ull n01 = mul2(vab.x, q1); n01 = fma2(vab.y, q0, n01);
            ull n23 = mul2(vcd.x, q3); n23 = fma2(vcd.y, q2, n23);
            ull den = mul2(d01, d23);
            ull num = mul2(n01, d23); num = fma2(n23, d01, num);
            float2 dd = unpk(den);
            ull rr = pk(frcp(dd.x), frcp(dd.y));
            acc1 = fma2(num, rr, acc1);
        }
    }

    // Output: transpose through ring -> coalesced STG.128
    cp_wait<0>();
    __syncthreads();
    float* Os = (float*)ring;
    float2 a0 = unpk(acc0), a1 = unpk(acc1);
    Os[0 * 128 + t] = fmaf(-2.0f, a0.x, Vsum);
    Os[1 * 128 + t] = fmaf(-2.0f, a0.y, Vsum);
    Os[2 * 128 + t] = fmaf(-2.0f, a1.x, Vsum);
    Os[3 * 128 + t] = fmaf(-2.0f, a1.y, Vsum);
    __syncthreads();
    {
        int j = t >> 5, kq = t & 31;
        float4 o = *(const float4*)&Os[j * 128 + kq * 4];
        *(float4*)&out[(size_t)(b * DD + j0 + j) * DD + kt * 128 + kq * 4] = o;
    }
}

// ---------------------------------------------------------------------------
extern "C" void kernel_launch(void* const* d_in, const int* in_sizes, int n_in,
                              void* d_out, int out_size)
{
    const float* X  = (const float*)d_in[0];
    const float* W1 = (const float*)d_in[1];
    const float* W2 = (const float*)d_in[2];
    const float* v  = (const float*)d_in[3];
    float* out      = (float*)d_out;

    fused_pairwise<<<GRID, 128>>>(X, W1, W2, v, out);
}

// round 7
// speedup vs baseline: 1.2152x; 1.2152x over previous
#include <cuda_runtime.h>

typedef unsigned long long ull;

// Problem: X[8,256,128], W1[128,128], W2[128,128], v[128] -> out[8,256,256]
#define BB   8
#define DD   256
#define DIM  128

// Scratch layouts tuned for k2:
//  g_EaT : [b][m][d]           (k2 loads 8-j runs with two LDG.128/thread)
//  g_Ec4 : [b][g=m/4][k][m%4]  (k2 streams one float4 per g per thread)
__device__ float g_EaT[BB * DIM * DD];
__device__ float g_Ec4[BB * 32 * DD * 4 + 8192];
__device__ float g_Vsum;

// ---- packed f32x2 helpers (Blackwell) --------------------------------------
__device__ __forceinline__ ull fma2(ull a, ull b, ull c) {
    ull d; asm("fma.rn.f32x2 %0,%1,%2,%3;" : "=l"(d) : "l"(a), "l"(b), "l"(c)); return d;
}
__device__ __forceinline__ ull mul2(ull a, ull b) {
    ull d; asm("mul.rn.f32x2 %0,%1,%2;" : "=l"(d) : "l"(a), "l"(b)); return d;
}
__device__ __forceinline__ ull dup2(float x) {
    ull d; asm("mov.b64 %0,{%1,%1};" : "=l"(d) : "f"(x)); return d;
}
__device__ __forceinline__ float2 unpk(ull a) {
    float2 r; asm("mov.b64 {%0,%1},%2;" : "=f"(r.x), "=f"(r.y) : "l"(a)); return r;
}
__device__ __forceinline__ ull pk(float x, float y) {
    ull d; asm("mov.b64 %0,{%1,%2};" : "=l"(d) : "f"(x), "f"(y)); return d;
}
__device__ __forceinline__ float frcp(float x) {
    float r; asm("rcp.approx.f32 %0,%1;" : "=f"(r) : "f"(x)); return r;
}
__device__ __forceinline__ void cp16(unsigned smem_dst, const void* gsrc) {
    asm volatile("cp.async.cg.shared.global [%0], [%1], 16;"
                 :: "r"(smem_dst), "l"(gsrc) : "memory");
}
__device__ __forceinline__ void cp_commit() {
    asm volatile("cp.async.commit_group;" ::: "memory");
}
template<int N> __device__ __forceinline__ void cp_wait() {
    asm volatile("cp.async.wait_group %0;" :: "n"(N) : "memory");
}

// 4-way rational combine for one packed j-pair:
// acc += (v0/q0 + v1/q1 + v2/q2 + v3/q3) with ONE rcp per 2 lanes.
__device__ __forceinline__ ull pair_acc(
    ull a0, ull a1, ull a2, ull a3,
    ull ec0, ull ec1, ull ec2, ull ec3,
    ull v0, ull v1, ull v2, ull v3,
    ull ONE2, ull acc)
{
    ull q0 = fma2(a0, ec0, ONE2);
    ull q1 = fma2(a1, ec1, ONE2);
    ull q2 = fma2(a2, ec2, ONE2);
    ull q3 = fma2(a3, ec3, ONE2);
    ull d01 = mul2(q0, q1), d23 = mul2(q2, q3);
    ull n01 = mul2(v0, q1); n01 = fma2(v1, q0, n01);
    ull n23 = mul2(v2, q3); n23 = fma2(v3, q2, n23);
    ull den = mul2(d01, d23);
    ull num = mul2(n01, d23); num = fma2(n23, d01, num);
    float2 dd = unpk(den);
    ull rr = pk(frcp(dd.x), frcp(dd.y));
    return fma2(num, rr, acc);
}

// ---------------------------------------------------------------------------
// Kernel 1: grid = 128 (64 tiles of 32 rows x 2 mats), 512 threads, 1/SM.
// FFMA2 main loop; outputs via conflict-free smem transposes -> STG.128.
// Block 0 also computes g_Vsum.
// ---------------------------------------------------------------------------
#define W_STRIDE 132
#define K1_SMEM ((DIM * W_STRIDE + 32 * DIM) * 4)   // 67584 + 16384 B

__global__ void __launch_bounds__(512, 1) k1_gemm_exp(
    const float* __restrict__ X,
    const float* __restrict__ W1,
    const float* __restrict__ W2,
    const float* __restrict__ v)
{
    extern __shared__ float sm[];
    float* Ws = sm;                        // 128 x 132 (reused as Es)
    float* Xs = sm + DIM * W_STRIDE;       // 32 x 128

    const int t       = threadIdx.x;
    const int mat     = blockIdx.x & 1;
    const int rowbase = (blockIdx.x >> 1) * 32;
    const float* W = mat ? W2 : W1;

    if (blockIdx.x == 0 && t < 32) {       // Vsum side-job
        float s = v[t] + v[t + 32] + v[t + 64] + v[t + 96];
        #pragma unroll
        for (int o = 16; o; o >>= 1) s += __shfl_xor_sync(0xffffffffu, s, o);
        if (t == 0) g_Vsum = s;
    }

    #pragma unroll
    for (int i = t; i < DIM * 32; i += 512) {
        int m  = i >> 5;
        int k4 = i & 31;
        *(float4*)&Ws[m * W_STRIDE + k4 * 4] = ((const float4*)W)[i];
    }
    #pragma unroll
    for (int i = t; i < 1024; i += 512)
        ((float4*)Xs)[i] = ((const float4*)X)[rowbase * 32 + i];
    __syncthreads();

    const int m  = t & 127;
    const int r0 = (t >> 7) * 8;

    ull acc[8];
    #pragma unroll
    for (int r = 0; r < 8; r++) acc[r] = dup2(0.0f);

    #pragma unroll 4
    for (int k4 = 0; k4 < 32; k4++) {
        ulonglong2 w = *(const ulonglong2*)&Ws[m * W_STRIDE + k4 * 4];
        #pragma unroll
        for (int r = 0; r < 8; r++) {
            ulonglong2 x = *(const ulonglong2*)&Xs[(r0 + r) * DIM + k4 * 4];
            acc[r] = fma2(w.x, x.x, acc[r]);
            acc[r] = fma2(w.y, x.y, acc[r]);
        }
    }

    float val[8];
    #pragma unroll
    for (int r = 0; r < 8; r++) {
        float2 a = unpk(acc[r]);
        val[r] = __expf(2.0f * (a.x + a.y));
    }

    cudaTriggerProgrammaticLaunchCompletion();

    const int b  = rowbase >> 8;
    const int d0 = rowbase & 255;
    float* Es = Ws;
    __syncthreads();

    if (mat == 0) {
        #pragma unroll
        for (int r = 0; r < 8; r++) Es[m * 33 + (r0 + r)] = val[r];
        __syncthreads();
        #pragma unroll
        for (int it = 0; it < 2; it++) {
            int idx = t + it * 512;
            int mm = idx >> 3, dq = idx & 7;
            float4 o;
            o.x = Es[mm * 33 + dq * 4 + 0];
            o.y = Es[mm * 33 + dq * 4 + 1];
            o.z = Es[mm * 33 + dq * 4 + 2];
            o.w = Es[mm * 33 + dq * 4 + 3];
            *(float4*)&g_EaT[(size_t)(b * DIM + mm) * DD + d0 + dq * 4] = o;
        }
    } else {
        #pragma unroll
        for (int r = 0; r < 8; r++) Es[(r0 + r) * 132 + m] = val[r];
        __syncthreads();
        #pragma unroll
        for (int it = 0; it < 2; it++) {
            int idx = t + it * 512;
            int g = idx >> 5, kl = idx & 31;
            float4 o = *(const float4*)&Es[kl * 132 + g * 4];
            *(float4*)&g_Ec4[((size_t)(b * 32 + g) * DD + d0 + kl) * 4] = o;
        }
    }
}

// ---------------------------------------------------------------------------
// Kernel 2 (PDL secondary): grid = 512 (8b x 32jg x 2kt), 128 threads,
// occ 4 (<=128 regs, single wave). Thread = 1 k, 8 j -> 4 independent
// packed j-pair chains per g: 2x ILP vs round 5 to hide the rcp chain.
// Ec streamed via cp.async 8-deep ring. Output via smem -> STG.128.
// ---------------------------------------------------------------------------
__global__ void __launch_bounds__(128, 4) k2_pairwise(
    const float* __restrict__ v,
    float* __restrict__ out)
{
    __shared__ __align__(16) float4 ring[8 * 128];   // 16KB Ec ring / Os
    __shared__ __align__(16) float4 EaL[DIM];        // [m] -> (a_j0..a_j3)
    __shared__ __align__(16) float4 EaH[DIM];        // [m] -> (a_j4..a_j7)
    __shared__ __align__(16) float2 vD[DIM];         // duplicated v

    const int t   = threadIdx.x;
    const int bid = blockIdx.x;
    const int kt  = bid & 1;
    const int jg  = (bid >> 1) & 31;
    const int b   = bid >> 6;
    const int j0  = jg * 8;
    const int k   = kt * 128 + t;

    {   // k1-independent prologue (overlaps k1 under PDL)
        float vv = v[t];
        vD[t] = make_float2(vv, vv);
    }

    cudaGridDependencySynchronize();

    {
        const float* ea = &g_EaT[(size_t)(b * DIM + t) * DD + j0];
        EaL[t] = *(const float4*)ea;
        EaH[t] = *(const float4*)(ea + 4);
    }

    const float4* ecq = (const float4*)g_Ec4 + (size_t)(b * 32) * DD + k;
    unsigned rb = (unsigned)__cvta_generic_to_shared(ring) + t * 16;

    #pragma unroll
    for (int s = 0; s < 7; s++) {
        cp16(rb + (s & 7) * 2048, ecq + (size_t)s * DD);
        cp_commit();
    }
    __syncthreads();

    const float Vsum = g_Vsum;
    const ull ONE2 = dup2(1.0f);
    ull acc0 = dup2(0.0f), acc1 = dup2(0.0f);
    ull acc2 = dup2(0.0f), acc3 = dup2(0.0f);

    #pragma unroll 4
    for (int g = 0; g < 32; g++) {
        cp_wait<6>();
        float4 E = ring[(g & 7) * 128 + t];
        if (g < 25)
            cp16(rb + ((g + 7) & 7) * 2048, ecq + (size_t)(g + 7) * DD);
        cp_commit();

        ull ec0 = dup2(E.x), ec1 = dup2(E.y), ec2 = dup2(E.z), ec3 = dup2(E.w);
        const ulonglong2* eL = (const ulonglong2*)(EaL + 4 * g);
        const ulonglong2* eH = (const ulonglong2*)(EaH + 4 * g);
        ulonglong2 l0 = eL[0], l1 = eL[1], l2 = eL[2], l3 = eL[3];
        ulonglong2 h0 = eH[0], h1 = eH[1], h2 = eH[2], h3 = eH[3];
        ulonglong2 vab = ((const ulonglong2*)vD)[2 * g];
        ulonglong2 vcd = ((const ulonglong2*)vD)[2 * g + 1];

        acc0 = pair_acc(l0.x, l1.x, l2.x, l3.x, ec0, ec1, ec2, ec3,
                        vab.x, vab.y, vcd.x, vcd.y, ONE2, acc0);
        acc1 = pair_acc(l0.y, l1.y, l2.y, l3.y, ec0, ec1, ec2, ec3,
                        vab.x, vab.y, vcd.x, vcd.y, ONE2, acc1);
        acc2 = pair_acc(h0.x, h1.x, h2.x, h3.x, ec0, ec1, ec2, ec3,
                        vab.x, vab.y, vcd.x, vcd.y, ONE2, acc2);
        acc3 = pair_acc(h0.y, h1.y, h2.y, h3.y, ec0, ec1, ec2, ec3,
                        vab.x, vab.y, vcd.x, vcd.y, ONE2, acc3);
    }

    // Output: transpose through ring -> coalesced STG.128
    cp_wait<0>();
    __syncthreads();
    float* Os = (float*)ring;              // 8 j x 128 k = 4KB
    float2 a0 = unpk(acc0), a1 = unpk(acc1);
    float2 a2 = unpk(acc2), a3 = unpk(acc3);
    Os[0 * 128 + t] = fmaf(-2.0f, a0.x, Vsum);
    Os[1 * 128 + t] = fmaf(-2.0f, a0.y, Vsum);
    Os[2 * 128 + t] = fmaf(-2.0f, a1.x, Vsum);
    Os[3 * 128 + t] = fmaf(-2.0f, a1.y, Vsum);
    Os[4 * 128 + t] = fmaf(-2.0f, a2.x, Vsum);
    Os[5 * 128 + t] = fmaf(-2.0f, a2.y, Vsum);
    Os[6 * 128 + t] = fmaf(-2.0f, a3.x, Vsum);
    Os[7 * 128 + t] = fmaf(-2.0f, a3.y, Vsum);
    __syncthreads();
    #pragma unroll
    for (int it = 0; it < 2; it++) {
        int idx = t + it * 128;
        int j = idx >> 5, kq = idx & 31;
        float4 o = *(const float4*)&Os[j * 128 + kq * 4];
        *(float4*)&out[(size_t)(b * DD + j0 + j) * DD + kt * 128 + kq * 4] = o;
    }
}

// ---------------------------------------------------------------------------
extern "C" void kernel_launch(void* const* d_in, const int* in_sizes, int n_in,
                              void* d_out, int out_size)
{
    const float* X  = (const float*)d_in[0];
    const float* W1 = (const float*)d_in[1];
    const float* W2 = (const float*)d_in[2];
    const float* v  = (const float*)d_in[3];
    float* out      = (float*)d_out;

    cudaFuncSetAttribute(k1_gemm_exp,
                         cudaFuncAttributeMaxDynamicSharedMemorySize, K1_SMEM);

    k1_gemm_exp<<<128, 512, K1_SMEM>>>(X, W1, W2, v);

    cudaLaunchAttribute attr[1];
    attr[0].id = cudaLaunchAttributeProgrammaticStreamSerialization;
    attr[0].val.programmaticStreamSerializationAllowed = 1;
    cudaLaunchConfig_t cfg = {};
    cfg.gridDim  = dim3(512, 1, 1);
    cfg.blockDim = dim3(128, 1, 1);
    cfg.dynamicSmemBytes = 0;
    cfg.stream = 0;
    cfg.attrs = attr;
    cfg.numAttrs = 1;
    cudaLaunchKernelEx(&cfg, k2_pairwise, v, out);
}

// round 8
// speedup vs baseline: 1.2252x; 1.0083x over previous
#include <cuda_runtime.h>

typedef unsigned long long ull;

// Problem: X[8,256,128], W1[128,128], W2[128,128], v[128] -> out[8,256,256]
#define BB   8
#define DD   256
#define DIM  128

// Scratch layouts tuned for k2:
//  g_EaT : [b][m][d]           (k2 loads j-quads with one LDG.128/thread)
//  g_Ec4 : [b][g=m/4][k][m%4]  (k2 streams one float4 per g per thread)
__device__ float g_EaT[BB * DIM * DD];
__device__ float g_Ec4[BB * 32 * DD * 4 + 8192];
__device__ float g_Vsum;

// ---- packed f32x2 helpers (Blackwell) --------------------------------------
__device__ __forceinline__ ull fma2(ull a, ull b, ull c) {
    ull d; asm("fma.rn.f32x2 %0,%1,%2,%3;" : "=l"(d) : "l"(a), "l"(b), "l"(c)); return d;
}
__device__ __forceinline__ ull mul2(ull a, ull b) {
    ull d; asm("mul.rn.f32x2 %0,%1,%2;" : "=l"(d) : "l"(a), "l"(b)); return d;
}
__device__ __forceinline__ ull dup2(float x) {
    ull d; asm("mov.b64 %0,{%1,%1};" : "=l"(d) : "f"(x)); return d;
}
__device__ __forceinline__ float2 unpk(ull a) {
    float2 r; asm("mov.b64 {%0,%1},%2;" : "=f"(r.x), "=f"(r.y) : "l"(a)); return r;
}
__device__ __forceinline__ ull pk(float x, float y) {
    ull d; asm("mov.b64 %0,{%1,%2};" : "=l"(d) : "f"(x), "f"(y)); return d;
}
__device__ __forceinline__ float frcp(float x) {
    float r; asm("rcp.approx.f32 %0,%1;" : "=f"(r) : "f"(x)); return r;
}

// 4-way rational combine for one packed j-pair:
// acc += (v0/q0 + v1/q1 + v2/q2 + v3/q3), ONE rcp per 2 lanes.
__device__ __forceinline__ ull pair_acc(
    ull a0, ull a1, ull a2, ull a3,
    ull ec0, ull ec1, ull ec2, ull ec3,
    ull v0, ull v1, ull v2, ull v3,
    ull ONE2, ull acc)
{
    ull q0 = fma2(a0, ec0, ONE2);
    ull q1 = fma2(a1, ec1, ONE2);
    ull q2 = fma2(a2, ec2, ONE2);
    ull q3 = fma2(a3, ec3, ONE2);
    ull d01 = mul2(q0, q1), d23 = mul2(q2, q3);
    ull n01 = mul2(v0, q1); n01 = fma2(v1, q0, n01);
    ull n23 = mul2(v2, q3); n23 = fma2(v3, q2, n23);
    ull den = mul2(d01, d23);
    ull num = mul2(n01, d23); num = fma2(n23, d01, num);
    float2 dd = unpk(den);
    ull rr = pk(frcp(dd.x), frcp(dd.y));
    return fma2(num, rr, acc);
}

// ---------------------------------------------------------------------------
// Kernel 1: grid = 128 (64 tiles of 32 rows x 2 mats), 512 threads, 1/SM.
// FFMA2 main loop; outputs via conflict-free smem transposes -> STG.128.
// Block 0 also computes g_Vsum.
// ---------------------------------------------------------------------------
#define W_STRIDE 132
#define K1_SMEM ((DIM * W_STRIDE + 32 * DIM) * 4)

__global__ void __launch_bounds__(512, 1) k1_gemm_exp(
    const float* __restrict__ X,
    const float* __restrict__ W1,
    const float* __restrict__ W2,
    const float* __restrict__ v)
{
    extern __shared__ float sm[];
    float* Ws = sm;                        // 128 x 132 (reused as Es)
    float* Xs = sm + DIM * W_STRIDE;       // 32 x 128

    const int t       = threadIdx.x;
    const int mat     = blockIdx.x & 1;
    const int rowbase = (blockIdx.x >> 1) * 32;
    const float* W = mat ? W2 : W1;

    if (blockIdx.x == 0 && t < 32) {       // Vsum side-job
        float s = v[t] + v[t + 32] + v[t + 64] + v[t + 96];
        #pragma unroll
        for (int o = 16; o; o >>= 1) s += __shfl_xor_sync(0xffffffffu, s, o);
        if (t == 0) g_Vsum = s;
    }

    #pragma unroll
    for (int i = t; i < DIM * 32; i += 512) {
        int m  = i >> 5;
        int k4 = i & 31;
        *(float4*)&Ws[m * W_STRIDE + k4 * 4] = ((const float4*)W)[i];
    }
    #pragma unroll
    for (int i = t; i < 1024; i += 512)
        ((float4*)Xs)[i] = ((const float4*)X)[rowbase * 32 + i];
    __syncthreads();

    const int m  = t & 127;
    const int r0 = (t >> 7) * 8;

    ull acc[8];
    #pragma unroll
    for (int r = 0; r < 8; r++) acc[r] = dup2(0.0f);

    #pragma unroll 4
    for (int k4 = 0; k4 < 32; k4++) {
        ulonglong2 w = *(const ulonglong2*)&Ws[m * W_STRIDE + k4 * 4];
        #pragma unroll
        for (int r = 0; r < 8; r++) {
            ulonglong2 x = *(const ulonglong2*)&Xs[(r0 + r) * DIM + k4 * 4];
            acc[r] = fma2(w.x, x.x, acc[r]);
            acc[r] = fma2(w.y, x.y, acc[r]);
        }
    }

    float val[8];
    #pragma unroll
    for (int r = 0; r < 8; r++) {
        float2 a = unpk(acc[r]);
        val[r] = __expf(2.0f * (a.x + a.y));
    }

    cudaTriggerProgrammaticLaunchCompletion();

    const int b  = rowbase >> 8;
    const int d0 = rowbase & 255;
    float* Es = Ws;
    __syncthreads();

    if (mat == 0) {
        #pragma unroll
        for (int r = 0; r < 8; r++) Es[m * 33 + (r0 + r)] = val[r];
        __syncthreads();
        #pragma unroll
        for (int it = 0; it < 2; it++) {
            int idx = t + it * 512;
            int mm = idx >> 3, dq = idx & 7;
            float4 o;
            o.x = Es[mm * 33 + dq * 4 + 0];
            o.y = Es[mm * 33 + dq * 4 + 1];
            o.z = Es[mm * 33 + dq * 4 + 2];
            o.w = Es[mm * 33 + dq * 4 + 3];
            *(float4*)&g_EaT[(size_t)(b * DIM + mm) * DD + d0 + dq * 4] = o;
        }
    } else {
        #pragma unroll
        for (int r = 0; r < 8; r++) Es[(r0 + r) * 132 + m] = val[r];
        __syncthreads();
        #pragma unroll
        for (int it = 0; it < 2; it++) {
            int idx = t + it * 512;
            int g = idx >> 5, kl = idx & 31;
            float4 o = *(const float4*)&Es[kl * 132 + g * 4];
            *(float4*)&g_Ec4[((size_t)(b * 32 + g) * DD + d0 + kl) * 4] = o;
        }
    }
}

// ---------------------------------------------------------------------------
// Kernel 2 (PDL secondary): grid = 2048 (8b x 64jg x 4 k-quarters),
// 64 threads, occ 16 (32 warps/SM, regfile exactly full at 64 regs).
// Thread = 1 k, 4 j. Ec LDG double-buffered; 4-way rational combine,
// packed FFMA2. Fine blocks -> smooth tail + high SM fill.
// ---------------------------------------------------------------------------
__global__ void __launch_bounds__(64, 16) k2_pairwise(
    const float* __restrict__ v,
    float* __restrict__ out)
{
    __shared__ __align__(16) float4 EaTf4[DIM];   // [m] -> (a_j0..a_j3)
    __shared__ __align__(16) float2 vD[DIM];      // duplicated v
    __shared__ __align__(16) float  Os[4 * 64];   // output transpose

    const int t   = threadIdx.x;
    const int bid = blockIdx.x;
    const int kt  = bid & 3;
    const int jg  = (bid >> 2) & 63;
    const int b   = bid >> 8;
    const int j0  = jg * 4;
    const int k   = kt * 64 + t;

    // k1-independent prologue (overlaps k1 under PDL)
    #pragma unroll
    for (int i = 0; i < 2; i++) {
        float vv = v[t + i * 64];
        vD[t + i * 64] = make_float2(vv, vv);
    }

    cudaGridDependencySynchronize();

    #pragma unroll
    for (int i = 0; i < 2; i++) {
        int m = t + i * 64;
        EaTf4[m] = *(const float4*)&g_EaT[(size_t)(b * DIM + m) * DD + j0];
    }
    __syncthreads();

    const float Vsum = g_Vsum;
    const ull ONE2 = dup2(1.0f);
    ull acc0 = dup2(0.0f), acc1 = dup2(0.0f);

    const float4* ecq = (const float4*)g_Ec4 + (size_t)(b * 32) * DD + k;
    float4 E = *ecq;                                   // g = 0

    #pragma unroll 2
    for (int g = 0; g < 32; g++) {
        float4 En = __ldg(ecq + (size_t)(g + 1) * DD); // padded tail @ g=31

        ull ec0 = dup2(E.x), ec1 = dup2(E.y), ec2 = dup2(E.z), ec3 = dup2(E.w);
        const ulonglong2* eap = (const ulonglong2*)(EaTf4 + 4 * g);
        ulonglong2 ea0 = eap[0], ea1 = eap[1], ea2 = eap[2], ea3 = eap[3];
        ulonglong2 vab = ((const ulonglong2*)vD)[2 * g];
        ulonglong2 vcd = ((const ulonglong2*)vD)[2 * g + 1];

        acc0 = pair_acc(ea0.x, ea1.x, ea2.x, ea3.x, ec0, ec1, ec2, ec3,
                        vab.x, vab.y, vcd.x, vcd.y, ONE2, acc0);
        acc1 = pair_acc(ea0.y, ea1.y, ea2.y, ea3.y, ec0, ec1, ec2, ec3,
                        vab.x, vab.y, vcd.x, vcd.y, ONE2, acc1);
        E = En;
    }

    // Output: transpose through smem -> coalesced STG.128
    __syncthreads();
    float2 a0 = unpk(acc0), a1 = unpk(acc1);
    Os[0 * 64 + t] = fmaf(-2.0f, a0.x, Vsum);
    Os[1 * 64 + t] = fmaf(-2.0f, a0.y, Vsum);
    Os[2 * 64 + t] = fmaf(-2.0f, a1.x, Vsum);
    Os[3 * 64 + t] = fmaf(-2.0f, a1.y, Vsum);
    __syncthreads();
    {
        int j = t >> 4, kq = t & 15;
        float4 o = *(const float4*)&Os[j * 64 + kq * 4];
        *(float4*)&out[(size_t)(b * DD + j0 + j) * DD + kt * 64 + kq * 4] = o;
    }
}

// ---------------------------------------------------------------------------
extern "C" void kernel_launch(void* const* d_in, const int* in_sizes, int n_in,
                              void* d_out, int out_size)
{
    const float* X  = (const float*)d_in[0];
    const float* W1 = (const float*)d_in[1];
    const float* W2 = (const float*)d_in[2];
    const float* v  = (const float*)d_in[3];
    float* out      = (float*)d_out;

    cudaFuncSetAttribute(k1_gemm_exp,
                         cudaFuncAttributeMaxDynamicSharedMemorySize, K1_SMEM);

    k1_gemm_exp<<<128, 512, K1_SMEM>>>(X, W1, W2, v);

    cudaLaunchAttribute attr[1];
    attr[0].id = cudaLaunchAttributeProgrammaticStreamSerialization;
    attr[0].val.programmaticStreamSerializationAllowed = 1;
    cudaLaunchConfig_t cfg = {};
    cfg.gridDim  = dim3(2048, 1, 1);
    cfg.blockDim = dim3(64, 1, 1);
    cfg.dynamicSmemBytes = 0;
    cfg.stream = 0;
    cfg.attrs = attr;
    cfg.numAttrs = 1;
    cudaLaunchKernelEx(&cfg, k2_pairwise, v, out);
}